// round 12
// baseline (speedup 1.0000x reference)
#include <cuda_runtime.h>
#include <math.h>

// SVDHead: weighted Kabsch over B=256 batches, N=65536 points.
// Kernel 1: streaming reduction, CHUNKS=8 (proven ~71.3us, ~83% HBM).
//           Writes partials TRANSPOSED so the solve reads them coalesced.
// Kernel 2: ONE block, 256 threads, one batch per thread. Uniform-control-flow
//           fixed-sweep Jacobi (no early exit, branchless degenerate case) +
//           coalesced partial loads -> kills both R10 failure modes.

#define B_DIM 256
#define N_DIM 65536
#define CHUNKS 8
#define TPB 256
#define NV 22   // 3 sum_s, 3 sum_t, 1 sum_w, 3 sum_ws, 3 sum_wt, 9 sum_w_s_t

// Transposed layout: g_scratch[(k*CHUNKS + c)*B_DIM + b]
__device__ float g_scratch[NV * CHUNKS * B_DIM];

// ---------------------------------------------------------------------------
// Kernel 1: per-(batch,chunk) partial reduction.
// ---------------------------------------------------------------------------
__global__ __launch_bounds__(TPB) void svd_reduce_kernel(
    const float* __restrict__ src,
    const float* __restrict__ tgt,
    const float* __restrict__ wgt)
{
    const int bc = blockIdx.x;
    const int b = bc >> 3;          // CHUNKS = 8
    const int c = bc & 7;

    const float4* s0 = (const float4*)(src + (size_t)b * 3 * N_DIM);
    const float4* s1 = s0 + (N_DIM / 4);
    const float4* s2 = s0 + 2 * (N_DIM / 4);
    const float4* t0 = (const float4*)(tgt + (size_t)b * 3 * N_DIM);
    const float4* t1 = t0 + (N_DIM / 4);
    const float4* t2 = t0 + 2 * (N_DIM / 4);
    const float4* w4 = (const float4*)(wgt + (size_t)b * N_DIM);

    const int base = c * (N_DIM / 4 / CHUNKS) + threadIdx.x;

    float a[NV];
#pragma unroll
    for (int k = 0; k < NV; k++) a[k] = 0.0f;

#define ACC_ONE(sx, sy, sz, tx, ty, tz, ww)                               \
    {                                                                     \
        a[0] += (sx); a[1] += (sy); a[2] += (sz);                         \
        a[3] += (tx); a[4] += (ty); a[5] += (tz);                         \
        a[6] += (ww);                                                     \
        float ws0 = (ww) * (sx), ws1 = (ww) * (sy), ws2 = (ww) * (sz);    \
        a[7] += ws0; a[8] += ws1; a[9] += ws2;                            \
        a[10] += (ww) * (tx); a[11] += (ww) * (ty); a[12] += (ww) * (tz); \
        a[13] += ws0 * (tx); a[14] += ws0 * (ty); a[15] += ws0 * (tz);    \
        a[16] += ws1 * (tx); a[17] += ws1 * (ty); a[18] += ws1 * (tz);    \
        a[19] += ws2 * (tx); a[20] += ws2 * (ty); a[21] += ws2 * (tz);    \
    }

#pragma unroll
    for (int k = 0; k < 8; k++) {
        const int idx = base + k * TPB;
        float4 vs0 = s0[idx], vs1 = s1[idx], vs2 = s2[idx];
        float4 vt0 = t0[idx], vt1 = t1[idx], vt2 = t2[idx];
        float4 vw  = w4[idx];
        ACC_ONE(vs0.x, vs1.x, vs2.x, vt0.x, vt1.x, vt2.x, vw.x);
        ACC_ONE(vs0.y, vs1.y, vs2.y, vt0.y, vt1.y, vt2.y, vw.y);
        ACC_ONE(vs0.z, vs1.z, vs2.z, vt0.z, vt1.z, vt2.z, vw.z);
        ACC_ONE(vs0.w, vs1.w, vs2.w, vt0.w, vt1.w, vt2.w, vw.w);
    }
#undef ACC_ONE

#pragma unroll
    for (int off = 16; off > 0; off >>= 1) {
#pragma unroll
        for (int k = 0; k < NV; k++)
            a[k] += __shfl_down_sync(0xFFFFFFFFu, a[k], off);
    }

    __shared__ float smem[TPB / 32][NV];
    const int warp = threadIdx.x >> 5;
    const int lane = threadIdx.x & 31;
    if (lane == 0) {
#pragma unroll
        for (int k = 0; k < NV; k++) smem[warp][k] = a[k];
    }
    __syncthreads();

    if (threadIdx.x < NV) {
        float s = 0.0f;
#pragma unroll
        for (int wgi = 0; wgi < TPB / 32; wgi++) s += smem[wgi][threadIdx.x];
        // Transposed: consecutive b at consecutive addresses for the solve.
        g_scratch[((size_t)threadIdx.x * CHUNKS + c) * B_DIM + b] = s;
    }
}

// ---------------------------------------------------------------------------
// Kernel 2: ONE block, 256 threads; thread b solves batch b (fp32).
// Coalesced partial loads; uniform-flow fixed-sweep Jacobi.
// ---------------------------------------------------------------------------
__global__ __launch_bounds__(TPB) void svd_solve_kernel(float* __restrict__ out)
{
    const int b = threadIdx.x;

    // Combine the CHUNKS partials in fixed order (deterministic). For each
    // (k,c), threads read consecutive addresses -> fully coalesced.
    float sums[NV];
#pragma unroll
    for (int k = 0; k < NV; k++) {
        float s = 0.0f;
#pragma unroll
        for (int c = 0; c < CHUNKS; c++)
            s += g_scratch[((size_t)k * CHUNKS + c) * B_DIM + b];
        sums[k] = s;
    }

    const float invN = 1.0f / (float)N_DIM;
    float ms[3], mt[3], Sws[3], Swt[3], Sw, M[3][3];
#pragma unroll
    for (int i = 0; i < 3; i++) {
        ms[i]  = sums[i] * invN;
        mt[i]  = sums[3 + i] * invN;
        Sws[i] = sums[7 + i];
        Swt[i] = sums[10 + i];
    }
    Sw = sums[6];
#pragma unroll
    for (int i = 0; i < 3; i++)
#pragma unroll
        for (int j = 0; j < 3; j++)
            M[i][j] = sums[13 + i * 3 + j];

    // H_ij = sum w s_i t_j - ms_i*sum(w t_j) - mt_j*sum(w s_i) + ms_i mt_j sum(w)
    float H[3][3];
#pragma unroll
    for (int i = 0; i < 3; i++)
#pragma unroll
        for (int j = 0; j < 3; j++)
            H[i][j] = M[i][j] - ms[i] * Swt[j] - mt[j] * Sws[i] + ms[i] * mt[j] * Sw;

    // S = H^T H (symmetric PSD)
    float S[3][3];
#pragma unroll
    for (int i = 0; i < 3; i++)
#pragma unroll
        for (int j = 0; j < 3; j++) {
            float acc = 0.0f;
#pragma unroll
            for (int k = 0; k < 3; k++) acc += H[k][i] * H[k][j];
            S[i][j] = acc;
        }

    // Cyclic Jacobi, FIXED 4 sweeps, uniform control flow (no early exit).
    // Degenerate apq ~ 0 handled branchlessly: force t = 0 (identity rotation).
    float V[3][3] = {{1, 0, 0}, {0, 1, 0}, {0, 0, 1}};
#pragma unroll
    for (int sweep = 0; sweep < 4; sweep++) {
#pragma unroll
        for (int pq = 0; pq < 3; pq++) {
            const int p = (pq == 2) ? 1 : 0;
            const int q = (pq == 0) ? 1 : 2;
            float apq = S[p][q];
            float theta = (S[q][q] - S[p][p]) * __fdividef(0.5f, apq);
            float t = copysignf(1.0f, theta) *
                      __fdividef(1.0f, fabsf(theta) + sqrtf(theta * theta + 1.0f));
            if (!(fabsf(apq) > 1e-30f)) t = 0.0f;   // SEL, uniform flow
            float cth = rsqrtf(1.0f + t * t);
            float sth = t * cth;
            float app = S[p][p], aqq = S[q][q];
            S[p][p] = app - t * apq;
            S[q][q] = aqq + t * apq;
            S[p][q] = S[q][p] = 0.0f;
            const int r = 3 - p - q;
            float arp = S[r][p], arq = S[r][q];
            S[r][p] = S[p][r] = cth * arp - sth * arq;
            S[r][q] = S[q][r] = sth * arp + cth * arq;
#pragma unroll
            for (int k = 0; k < 3; k++) {
                float vkp = V[k][p], vkq = V[k][q];
                V[k][p] = cth * vkp - sth * vkq;
                V[k][q] = sth * vkp + cth * vkq;
            }
        }
    }

    // Sort eigenvalues descending; take top-2 eigenvectors.
    float lam[3] = {S[0][0], S[1][1], S[2][2]};
    int i0 = 0, i1 = 1, i2 = 2, tmp;
    if (lam[i0] < lam[i1]) { tmp = i0; i0 = i1; i1 = tmp; }
    if (lam[i0] < lam[i2]) { tmp = i0; i0 = i2; i2 = tmp; }
    if (lam[i1] < lam[i2]) { tmp = i1; i1 = i2; i2 = tmp; }

    float v1[3] = {V[0][i0], V[1][i0], V[2][i0]};
    float v2[3] = {V[0][i1], V[1][i1], V[2][i1]};
    float v3[3] = {v1[1] * v2[2] - v1[2] * v2[1],
                   v1[2] * v2[0] - v1[0] * v2[2],
                   v1[0] * v2[1] - v1[1] * v2[0]};

    // u1 = normalize(H v1); u2 = normalize(GS(H v2, u1)); u3 = u1 x u2.
    float u1[3], u2[3], u3[3];
#pragma unroll
    for (int i = 0; i < 3; i++)
        u1[i] = H[i][0] * v1[0] + H[i][1] * v1[1] + H[i][2] * v1[2];
    float in1 = rsqrtf(u1[0] * u1[0] + u1[1] * u1[1] + u1[2] * u1[2] + 1e-35f);
#pragma unroll
    for (int i = 0; i < 3; i++) u1[i] *= in1;

#pragma unroll
    for (int i = 0; i < 3; i++)
        u2[i] = H[i][0] * v2[0] + H[i][1] * v2[1] + H[i][2] * v2[2];
    float d12 = u2[0] * u1[0] + u2[1] * u1[1] + u2[2] * u1[2];
#pragma unroll
    for (int i = 0; i < 3; i++) u2[i] -= d12 * u1[i];
    float in2 = rsqrtf(u2[0] * u2[0] + u2[1] * u2[1] + u2[2] * u2[2] + 1e-35f);
#pragma unroll
    for (int i = 0; i < 3; i++) u2[i] *= in2;

    u3[0] = u1[1] * u2[2] - u1[2] * u2[1];
    u3[1] = u1[2] * u2[0] - u1[0] * u2[2];
    u3[2] = u1[0] * u2[1] - u1[1] * u2[0];

    // R = v1 u1^T + v2 u2^T + v3 u3^T (proper rotation, det=+1).
    float R[3][3];
#pragma unroll
    for (int i = 0; i < 3; i++)
#pragma unroll
        for (int j = 0; j < 3; j++)
            R[i][j] = v1[i] * u1[j] + v2[i] * u2[j] + v3[i] * u3[j];

    // t = -R @ src_mean + tgt_mean ; t_out = -R^T t ; Rt = R^T
    float tv[3];
#pragma unroll
    for (int i = 0; i < 3; i++)
        tv[i] = -(R[i][0] * ms[0] + R[i][1] * ms[1] + R[i][2] * ms[2]) + mt[i];

    float* outR = out + (size_t)b * 9;
    float* outT = out + (size_t)B_DIM * 9 + (size_t)b * 3;
#pragma unroll
    for (int i = 0; i < 3; i++) {
#pragma unroll
        for (int j = 0; j < 3; j++)
            outR[i * 3 + j] = R[j][i];  // Rt = R^T
        outT[i] = -(R[0][i] * tv[0] + R[1][i] * tv[1] + R[2][i] * tv[2]);
    }
}

extern "C" void kernel_launch(void* const* d_in, const int* in_sizes, int n_in,
                              void* d_out, int out_size)
{
    const float* src = (const float*)d_in[0];
    const float* tgt = (const float*)d_in[1];
    const float* wgt = (const float*)d_in[2];
    float* out = (float*)d_out;

    svd_reduce_kernel<<<B_DIM * CHUNKS, TPB>>>(src, tgt, wgt);
    svd_solve_kernel<<<1, TPB>>>(out);
}

// round 13
// speedup vs baseline: 1.0917x; 1.0917x over previous
#include <cuda_runtime.h>
#include <math.h>

// SVDHead: weighted Kabsch over B=256 batches, N=65536 points.
// Kernel 1: streaming reduction, CHUNKS=8 (proven ~71.3us, ~84% DRAM).
// Kernel 2: 256 blocks x 32 threads, fp32 Jacobi solve (proven 6.9us shape),
//           launched with PDL so dispatch/ramp overlaps the reduce tail.

#define B_DIM 256
#define N_DIM 65536
#define CHUNKS 8
#define TPB 256
#define NV 22   // 3 sum_s, 3 sum_t, 1 sum_w, 3 sum_ws, 3 sum_wt, 9 sum_w_s_t

__device__ float g_scratch[B_DIM * CHUNKS * NV];

// ---------------------------------------------------------------------------
// Kernel 1: per-(batch,chunk) partial reduction (R6-proven hot loop).
// Early PDL trigger right after the partial store.
// ---------------------------------------------------------------------------
__global__ __launch_bounds__(TPB) void svd_reduce_kernel(
    const float* __restrict__ src,
    const float* __restrict__ tgt,
    const float* __restrict__ wgt)
{
    const int bc = blockIdx.x;
    const int b = bc >> 3;          // CHUNKS = 8
    const int c = bc & 7;

    const float4* s0 = (const float4*)(src + (size_t)b * 3 * N_DIM);
    const float4* s1 = s0 + (N_DIM / 4);
    const float4* s2 = s0 + 2 * (N_DIM / 4);
    const float4* t0 = (const float4*)(tgt + (size_t)b * 3 * N_DIM);
    const float4* t1 = t0 + (N_DIM / 4);
    const float4* t2 = t0 + 2 * (N_DIM / 4);
    const float4* w4 = (const float4*)(wgt + (size_t)b * N_DIM);

    const int base = c * (N_DIM / 4 / CHUNKS) + threadIdx.x;

    float a[NV];
#pragma unroll
    for (int k = 0; k < NV; k++) a[k] = 0.0f;

#define ACC_ONE(sx, sy, sz, tx, ty, tz, ww)                               \
    {                                                                     \
        a[0] += (sx); a[1] += (sy); a[2] += (sz);                         \
        a[3] += (tx); a[4] += (ty); a[5] += (tz);                         \
        a[6] += (ww);                                                     \
        float ws0 = (ww) * (sx), ws1 = (ww) * (sy), ws2 = (ww) * (sz);    \
        a[7] += ws0; a[8] += ws1; a[9] += ws2;                            \
        a[10] += (ww) * (tx); a[11] += (ww) * (ty); a[12] += (ww) * (tz); \
        a[13] += ws0 * (tx); a[14] += ws0 * (ty); a[15] += ws0 * (tz);    \
        a[16] += ws1 * (tx); a[17] += ws1 * (ty); a[18] += ws1 * (tz);    \
        a[19] += ws2 * (tx); a[20] += ws2 * (ty); a[21] += ws2 * (tz);    \
    }

#pragma unroll
    for (int k = 0; k < 8; k++) {
        const int idx = base + k * TPB;
        float4 vs0 = s0[idx], vs1 = s1[idx], vs2 = s2[idx];
        float4 vt0 = t0[idx], vt1 = t1[idx], vt2 = t2[idx];
        float4 vw  = w4[idx];
        ACC_ONE(vs0.x, vs1.x, vs2.x, vt0.x, vt1.x, vt2.x, vw.x);
        ACC_ONE(vs0.y, vs1.y, vs2.y, vt0.y, vt1.y, vt2.y, vw.y);
        ACC_ONE(vs0.z, vs1.z, vs2.z, vt0.z, vt1.z, vt2.z, vw.z);
        ACC_ONE(vs0.w, vs1.w, vs2.w, vt0.w, vt1.w, vt2.w, vw.w);
    }
#undef ACC_ONE

#pragma unroll
    for (int off = 16; off > 0; off >>= 1) {
#pragma unroll
        for (int k = 0; k < NV; k++)
            a[k] += __shfl_down_sync(0xFFFFFFFFu, a[k], off);
    }

    __shared__ float smem[TPB / 32][NV];
    const int warp = threadIdx.x >> 5;
    const int lane = threadIdx.x & 31;
    if (lane == 0) {
#pragma unroll
        for (int k = 0; k < NV; k++) smem[warp][k] = a[k];
    }
    __syncthreads();

    if (threadIdx.x < NV) {
        float s = 0.0f;
#pragma unroll
        for (int wgi = 0; wgi < TPB / 32; wgi++) s += smem[wgi][threadIdx.x];
        g_scratch[(size_t)bc * NV + threadIdx.x] = s;
        __threadfence();   // make partials globally visible before trigger
    }
    __syncthreads();

#if __CUDA_ARCH__ >= 900
    // Early PDL trigger: once every block has triggered, the solve kernel's
    // blocks dispatch while this grid drains.
    cudaTriggerProgrammaticLaunchCompletion();
#endif
}

// ---------------------------------------------------------------------------
// Kernel 2: per-batch solve. grid = B blocks, 32 threads (proven layout).
// Opens with grid-dependency sync (PDL).
// ---------------------------------------------------------------------------
__global__ __launch_bounds__(32) void svd_solve_kernel(float* __restrict__ out)
{
#if __CUDA_ARCH__ >= 900
    cudaGridDependencySynchronize();
#endif

    const int b = blockIdx.x;
    __shared__ float sums[NV];

    if (threadIdx.x < NV) {
        float s = 0.0f;
#pragma unroll
        for (int c = 0; c < CHUNKS; c++)
            s += g_scratch[((size_t)b * CHUNKS + c) * NV + threadIdx.x];
        sums[threadIdx.x] = s;
    }
    __syncthreads();

    if (threadIdx.x != 0) return;

    const float invN = 1.0f / (float)N_DIM;
    float ms[3], mt[3], Sws[3], Swt[3], Sw, M[3][3];
#pragma unroll
    for (int i = 0; i < 3; i++) {
        ms[i]  = sums[i] * invN;
        mt[i]  = sums[3 + i] * invN;
        Sws[i] = sums[7 + i];
        Swt[i] = sums[10 + i];
    }
    Sw = sums[6];
#pragma unroll
    for (int i = 0; i < 3; i++)
#pragma unroll
        for (int j = 0; j < 3; j++)
            M[i][j] = sums[13 + i * 3 + j];

    // H_ij = sum w s_i t_j - ms_i*sum(w t_j) - mt_j*sum(w s_i) + ms_i mt_j sum(w)
    float H[3][3];
#pragma unroll
    for (int i = 0; i < 3; i++)
#pragma unroll
        for (int j = 0; j < 3; j++)
            H[i][j] = M[i][j] - ms[i] * Swt[j] - mt[j] * Sws[i] + ms[i] * mt[j] * Sw;

    // S = H^T H (symmetric PSD)
    float S[3][3];
#pragma unroll
    for (int i = 0; i < 3; i++)
#pragma unroll
        for (int j = 0; j < 3; j++) {
            float acc = 0.0f;
#pragma unroll
            for (int k = 0; k < 3; k++) acc += H[k][i] * H[k][j];
            S[i][j] = acc;
        }

    const float trS = S[0][0] + S[1][1] + S[2][2];
    const float tol = 1e-13f * trS * trS + 1e-35f;

    // Cyclic Jacobi eigen-decomposition in fp32: S = V diag(l) V^T.
    float V[3][3] = {{1, 0, 0}, {0, 1, 0}, {0, 0, 1}};
    for (int sweep = 0; sweep < 5; sweep++) {
        float offm = S[0][1] * S[0][1] + S[0][2] * S[0][2] + S[1][2] * S[1][2];
        if (offm < tol) break;
#pragma unroll
        for (int pq = 0; pq < 3; pq++) {
            const int p = (pq == 2) ? 1 : 0;
            const int q = (pq == 0) ? 1 : 2;
            float apq = S[p][q];
            if (fabsf(apq) < 1e-30f) continue;
            float theta = (S[q][q] - S[p][p]) * __fdividef(0.5f, apq);
            float t = copysignf(1.0f, theta) *
                      __fdividef(1.0f, fabsf(theta) + sqrtf(theta * theta + 1.0f));
            float cth = rsqrtf(1.0f + t * t);
            float sth = t * cth;
            float app = S[p][p], aqq = S[q][q];
            S[p][p] = app - t * apq;
            S[q][q] = aqq + t * apq;
            S[p][q] = S[q][p] = 0.0f;
            const int r = 3 - p - q;
            float arp = S[r][p], arq = S[r][q];
            S[r][p] = S[p][r] = cth * arp - sth * arq;
            S[r][q] = S[q][r] = sth * arp + cth * arq;
#pragma unroll
            for (int k = 0; k < 3; k++) {
                float vkp = V[k][p], vkq = V[k][q];
                V[k][p] = cth * vkp - sth * vkq;
                V[k][q] = sth * vkp + cth * vkq;
            }
        }
    }

    // Sort eigenvalues descending; take top-2 eigenvectors.
    float lam[3] = {S[0][0], S[1][1], S[2][2]};
    int i0 = 0, i1 = 1, i2 = 2, tmp;
    if (lam[i0] < lam[i1]) { tmp = i0; i0 = i1; i1 = tmp; }
    if (lam[i0] < lam[i2]) { tmp = i0; i0 = i2; i2 = tmp; }
    if (lam[i1] < lam[i2]) { tmp = i1; i1 = i2; i2 = tmp; }

    float v1[3] = {V[0][i0], V[1][i0], V[2][i0]};
    float v2[3] = {V[0][i1], V[1][i1], V[2][i1]};
    float v3[3] = {v1[1] * v2[2] - v1[2] * v2[1],
                   v1[2] * v2[0] - v1[0] * v2[2],
                   v1[0] * v2[1] - v1[1] * v2[0]};

    // u1 = normalize(H v1); u2 = normalize(GS(H v2, u1)); u3 = u1 x u2.
    float u1[3], u2[3], u3[3];
#pragma unroll
    for (int i = 0; i < 3; i++)
        u1[i] = H[i][0] * v1[0] + H[i][1] * v1[1] + H[i][2] * v1[2];
    float in1 = rsqrtf(u1[0] * u1[0] + u1[1] * u1[1] + u1[2] * u1[2] + 1e-35f);
#pragma unroll
    for (int i = 0; i < 3; i++) u1[i] *= in1;

#pragma unroll
    for (int i = 0; i < 3; i++)
        u2[i] = H[i][0] * v2[0] + H[i][1] * v2[1] + H[i][2] * v2[2];
    float d12 = u2[0] * u1[0] + u2[1] * u1[1] + u2[2] * u1[2];
#pragma unroll
    for (int i = 0; i < 3; i++) u2[i] -= d12 * u1[i];
    float in2 = rsqrtf(u2[0] * u2[0] + u2[1] * u2[1] + u2[2] * u2[2] + 1e-35f);
#pragma unroll
    for (int i = 0; i < 3; i++) u2[i] *= in2;

    u3[0] = u1[1] * u2[2] - u1[2] * u2[1];
    u3[1] = u1[2] * u2[0] - u1[0] * u2[2];
    u3[2] = u1[0] * u2[1] - u1[1] * u2[0];

    // R = v1 u1^T + v2 u2^T + v3 u3^T (proper rotation, det=+1).
    float R[3][3];
#pragma unroll
    for (int i = 0; i < 3; i++)
#pragma unroll
        for (int j = 0; j < 3; j++)
            R[i][j] = v1[i] * u1[j] + v2[i] * u2[j] + v3[i] * u3[j];

    // t = -R @ src_mean + tgt_mean ; t_out = -R^T t ; Rt = R^T
    float tv[3];
#pragma unroll
    for (int i = 0; i < 3; i++)
        tv[i] = -(R[i][0] * ms[0] + R[i][1] * ms[1] + R[i][2] * ms[2]) + mt[i];

    float* outR = out + (size_t)b * 9;
    float* outT = out + (size_t)B_DIM * 9 + (size_t)b * 3;
#pragma unroll
    for (int i = 0; i < 3; i++) {
#pragma unroll
        for (int j = 0; j < 3; j++)
            outR[i * 3 + j] = R[j][i];  // Rt = R^T
        outT[i] = -(R[0][i] * tv[0] + R[1][i] * tv[1] + R[2][i] * tv[2]);
    }
}

extern "C" void kernel_launch(void* const* d_in, const int* in_sizes, int n_in,
                              void* d_out, int out_size)
{
    const float* src = (const float*)d_in[0];
    const float* tgt = (const float*)d_in[1];
    const float* wgt = (const float*)d_in[2];
    float* out = (float*)d_out;

    svd_reduce_kernel<<<B_DIM * CHUNKS, TPB>>>(src, tgt, wgt);

    // Solve kernel with PDL: dispatch overlaps the reduce's drain.
    cudaLaunchAttribute attrs[1];
    attrs[0].id = cudaLaunchAttributeProgrammaticStreamSerialization;
    attrs[0].val.programmaticStreamSerializationAllowed = 1;

    cudaLaunchConfig_t cfg = {};
    cfg.gridDim  = dim3(B_DIM, 1, 1);
    cfg.blockDim = dim3(32, 1, 1);
    cfg.dynamicSmemBytes = 0;
    cfg.stream = 0;   // capture stream
    cfg.attrs = attrs;
    cfg.numAttrs = 1;

    cudaLaunchKernelEx(&cfg, svd_solve_kernel, out);
}

// round 14
// speedup vs baseline: 1.1189x; 1.0249x over previous
#include <cuda_runtime.h>
#include <math.h>

// SVDHead: weighted Kabsch over B=256 batches, N=65536 points.
// Kernel 1: streaming reduction, CHUNKS=8 (proven ~71.3us, ~82% of HBM spec).
// Kernel 2: 64 blocks x 128 threads, ONE batch per WARP -> single wave over
//           the chip (R13 insight: 256x32 = 2 waves explained the 6.9us floor;
//           algorithm changes never moved it).

#define B_DIM 256
#define N_DIM 65536
#define CHUNKS 8
#define TPB 256
#define NV 22   // 3 sum_s, 3 sum_t, 1 sum_w, 3 sum_ws, 3 sum_wt, 9 sum_w_s_t

__device__ float g_scratch[B_DIM * CHUNKS * NV];

// ---------------------------------------------------------------------------
// Kernel 1: per-(batch,chunk) partial reduction (R6-proven, untouched).
// ---------------------------------------------------------------------------
__global__ __launch_bounds__(TPB) void svd_reduce_kernel(
    const float* __restrict__ src,
    const float* __restrict__ tgt,
    const float* __restrict__ wgt)
{
    const int bc = blockIdx.x;
    const int b = bc >> 3;          // CHUNKS = 8
    const int c = bc & 7;

    const float4* s0 = (const float4*)(src + (size_t)b * 3 * N_DIM);
    const float4* s1 = s0 + (N_DIM / 4);
    const float4* s2 = s0 + 2 * (N_DIM / 4);
    const float4* t0 = (const float4*)(tgt + (size_t)b * 3 * N_DIM);
    const float4* t1 = t0 + (N_DIM / 4);
    const float4* t2 = t0 + 2 * (N_DIM / 4);
    const float4* w4 = (const float4*)(wgt + (size_t)b * N_DIM);

    const int base = c * (N_DIM / 4 / CHUNKS) + threadIdx.x;

    float a[NV];
#pragma unroll
    for (int k = 0; k < NV; k++) a[k] = 0.0f;

#define ACC_ONE(sx, sy, sz, tx, ty, tz, ww)                               \
    {                                                                     \
        a[0] += (sx); a[1] += (sy); a[2] += (sz);                         \
        a[3] += (tx); a[4] += (ty); a[5] += (tz);                         \
        a[6] += (ww);                                                     \
        float ws0 = (ww) * (sx), ws1 = (ww) * (sy), ws2 = (ww) * (sz);    \
        a[7] += ws0; a[8] += ws1; a[9] += ws2;                            \
        a[10] += (ww) * (tx); a[11] += (ww) * (ty); a[12] += (ww) * (tz); \
        a[13] += ws0 * (tx); a[14] += ws0 * (ty); a[15] += ws0 * (tz);    \
        a[16] += ws1 * (tx); a[17] += ws1 * (ty); a[18] += ws1 * (tz);    \
        a[19] += ws2 * (tx); a[20] += ws2 * (ty); a[21] += ws2 * (tz);    \
    }

#pragma unroll
    for (int k = 0; k < 8; k++) {
        const int idx = base + k * TPB;
        float4 vs0 = s0[idx], vs1 = s1[idx], vs2 = s2[idx];
        float4 vt0 = t0[idx], vt1 = t1[idx], vt2 = t2[idx];
        float4 vw  = w4[idx];
        ACC_ONE(vs0.x, vs1.x, vs2.x, vt0.x, vt1.x, vt2.x, vw.x);
        ACC_ONE(vs0.y, vs1.y, vs2.y, vt0.y, vt1.y, vt2.y, vw.y);
        ACC_ONE(vs0.z, vs1.z, vs2.z, vt0.z, vt1.z, vt2.z, vw.z);
        ACC_ONE(vs0.w, vs1.w, vs2.w, vt0.w, vt1.w, vt2.w, vw.w);
    }
#undef ACC_ONE

#pragma unroll
    for (int off = 16; off > 0; off >>= 1) {
#pragma unroll
        for (int k = 0; k < NV; k++)
            a[k] += __shfl_down_sync(0xFFFFFFFFu, a[k], off);
    }

    __shared__ float smem[TPB / 32][NV];
    const int warp = threadIdx.x >> 5;
    const int lane = threadIdx.x & 31;
    if (lane == 0) {
#pragma unroll
        for (int k = 0; k < NV; k++) smem[warp][k] = a[k];
    }
    __syncthreads();

    if (threadIdx.x < NV) {
        float s = 0.0f;
#pragma unroll
        for (int wgi = 0; wgi < TPB / 32; wgi++) s += smem[wgi][threadIdx.x];
        g_scratch[(size_t)bc * NV + threadIdx.x] = s;
    }
}

// ---------------------------------------------------------------------------
// Kernel 2: 64 blocks x 128 threads; warp w solves batch blockIdx*4 + w.
// Single wave over the chip; no smem, no __syncthreads.
// ---------------------------------------------------------------------------
__global__ __launch_bounds__(128) void svd_solve_kernel(float* __restrict__ out)
{
    const int wid  = threadIdx.x >> 5;
    const int lane = threadIdx.x & 31;
    const int b    = blockIdx.x * 4 + wid;

    // Lanes 0..21 each sum their statistic over the 8 chunks (L2 hits),
    // then 22 shfls deliver all statistics to every lane (lane 0 uses them).
    float s = 0.0f;
    if (lane < NV) {
#pragma unroll
        for (int c = 0; c < CHUNKS; c++)
            s += g_scratch[((size_t)b * CHUNKS + c) * NV + lane];
    }

    float sums[NV];
#pragma unroll
    for (int k = 0; k < NV; k++)
        sums[k] = __shfl_sync(0xFFFFFFFFu, s, k);

    if (lane != 0) return;

    const float invN = 1.0f / (float)N_DIM;
    float ms[3], mt[3], Sws[3], Swt[3], Sw, M[3][3];
#pragma unroll
    for (int i = 0; i < 3; i++) {
        ms[i]  = sums[i] * invN;
        mt[i]  = sums[3 + i] * invN;
        Sws[i] = sums[7 + i];
        Swt[i] = sums[10 + i];
    }
    Sw = sums[6];
#pragma unroll
    for (int i = 0; i < 3; i++)
#pragma unroll
        for (int j = 0; j < 3; j++)
            M[i][j] = sums[13 + i * 3 + j];

    // H_ij = sum w s_i t_j - ms_i*sum(w t_j) - mt_j*sum(w s_i) + ms_i mt_j sum(w)
    float H[3][3];
#pragma unroll
    for (int i = 0; i < 3; i++)
#pragma unroll
        for (int j = 0; j < 3; j++)
            H[i][j] = M[i][j] - ms[i] * Swt[j] - mt[j] * Sws[i] + ms[i] * mt[j] * Sw;

    // S = H^T H (symmetric PSD)
    float S[3][3];
#pragma unroll
    for (int i = 0; i < 3; i++)
#pragma unroll
        for (int j = 0; j < 3; j++) {
            float acc = 0.0f;
#pragma unroll
            for (int k = 0; k < 3; k++) acc += H[k][i] * H[k][j];
            S[i][j] = acc;
        }

    const float trS = S[0][0] + S[1][1] + S[2][2];
    const float tol = 1e-13f * trS * trS + 1e-35f;

    // Cyclic Jacobi eigen-decomposition in fp32: S = V diag(l) V^T.
    float V[3][3] = {{1, 0, 0}, {0, 1, 0}, {0, 0, 1}};
    for (int sweep = 0; sweep < 5; sweep++) {
        float offm = S[0][1] * S[0][1] + S[0][2] * S[0][2] + S[1][2] * S[1][2];
        if (offm < tol) break;
#pragma unroll
        for (int pq = 0; pq < 3; pq++) {
            const int p = (pq == 2) ? 1 : 0;
            const int q = (pq == 0) ? 1 : 2;
            float apq = S[p][q];
            if (fabsf(apq) < 1e-30f) continue;
            float theta = (S[q][q] - S[p][p]) * __fdividef(0.5f, apq);
            float t = copysignf(1.0f, theta) *
                      __fdividef(1.0f, fabsf(theta) + sqrtf(theta * theta + 1.0f));
            float cth = rsqrtf(1.0f + t * t);
            float sth = t * cth;
            float app = S[p][p], aqq = S[q][q];
            S[p][p] = app - t * apq;
            S[q][q] = aqq + t * apq;
            S[p][q] = S[q][p] = 0.0f;
            const int r = 3 - p - q;
            float arp = S[r][p], arq = S[r][q];
            S[r][p] = S[p][r] = cth * arp - sth * arq;
            S[r][q] = S[q][r] = sth * arp + cth * arq;
#pragma unroll
            for (int k = 0; k < 3; k++) {
                float vkp = V[k][p], vkq = V[k][q];
                V[k][p] = cth * vkp - sth * vkq;
                V[k][q] = sth * vkp + cth * vkq;
            }
        }
    }

    // Sort eigenvalues descending; take top-2 eigenvectors.
    float lam[3] = {S[0][0], S[1][1], S[2][2]};
    int i0 = 0, i1 = 1, i2 = 2, tmp;
    if (lam[i0] < lam[i1]) { tmp = i0; i0 = i1; i1 = tmp; }
    if (lam[i0] < lam[i2]) { tmp = i0; i0 = i2; i2 = tmp; }
    if (lam[i1] < lam[i2]) { tmp = i1; i1 = i2; i2 = tmp; }

    float v1[3] = {V[0][i0], V[1][i0], V[2][i0]};
    float v2[3] = {V[0][i1], V[1][i1], V[2][i1]};
    float v3[3] = {v1[1] * v2[2] - v1[2] * v2[1],
                   v1[2] * v2[0] - v1[0] * v2[2],
                   v1[0] * v2[1] - v1[1] * v2[0]};

    // u1 = normalize(H v1); u2 = normalize(GS(H v2, u1)); u3 = u1 x u2.
    float u1[3], u2[3], u3[3];
#pragma unroll
    for (int i = 0; i < 3; i++)
        u1[i] = H[i][0] * v1[0] + H[i][1] * v1[1] + H[i][2] * v1[2];
    float in1 = rsqrtf(u1[0] * u1[0] + u1[1] * u1[1] + u1[2] * u1[2] + 1e-35f);
#pragma unroll
    for (int i = 0; i < 3; i++) u1[i] *= in1;

#pragma unroll
    for (int i = 0; i < 3; i++)
        u2[i] = H[i][0] * v2[0] + H[i][1] * v2[1] + H[i][2] * v2[2];
    float d12 = u2[0] * u1[0] + u2[1] * u1[1] + u2[2] * u1[2];
#pragma unroll
    for (int i = 0; i < 3; i++) u2[i] -= d12 * u1[i];
    float in2 = rsqrtf(u2[0] * u2[0] + u2[1] * u2[1] + u2[2] * u2[2] + 1e-35f);
#pragma unroll
    for (int i = 0; i < 3; i++) u2[i] *= in2;

    u3[0] = u1[1] * u2[2] - u1[2] * u2[1];
    u3[1] = u1[2] * u2[0] - u1[0] * u2[2];
    u3[2] = u1[0] * u2[1] - u1[1] * u2[0];

    // R = v1 u1^T + v2 u2^T + v3 u3^T (proper rotation, det=+1).
    float R[3][3];
#pragma unroll
    for (int i = 0; i < 3; i++)
#pragma unroll
        for (int j = 0; j < 3; j++)
            R[i][j] = v1[i] * u1[j] + v2[i] * u2[j] + v3[i] * u3[j];

    // t = -R @ src_mean + tgt_mean ; t_out = -R^T t ; Rt = R^T
    float tv[3];
#pragma unroll
    for (int i = 0; i < 3; i++)
        tv[i] = -(R[i][0] * ms[0] + R[i][1] * ms[1] + R[i][2] * ms[2]) + mt[i];

    float* outR = out + (size_t)b * 9;
    float* outT = out + (size_t)B_DIM * 9 + (size_t)b * 3;
#pragma unroll
    for (int i = 0; i < 3; i++) {
#pragma unroll
        for (int j = 0; j < 3; j++)
            outR[i * 3 + j] = R[j][i];  // Rt = R^T
        outT[i] = -(R[0][i] * tv[0] + R[1][i] * tv[1] + R[2][i] * tv[2]);
    }
}

extern "C" void kernel_launch(void* const* d_in, const int* in_sizes, int n_in,
                              void* d_out, int out_size)
{
    const float* src = (const float*)d_in[0];
    const float* tgt = (const float*)d_in[1];
    const float* wgt = (const float*)d_in[2];
    float* out = (float*)d_out;

    svd_reduce_kernel<<<B_DIM * CHUNKS, TPB>>>(src, tgt, wgt);
    svd_solve_kernel<<<B_DIM / 4, 128>>>(out);
}

// round 15
// speedup vs baseline: 1.1485x; 1.0264x over previous
#include <cuda_runtime.h>
#include <math.h>

// SVDHead: weighted Kabsch over B=256 batches, N=65536 points.
// Kernel 1: streaming reduction, CHUNKS=16 (finer tail granularity vs R6's
//           CHUNKS=8: 4096 half-size blocks -> smaller partial-wave stranding).
// Kernel 2: 64 blocks x 128 threads, one batch per warp, single wave (R14).

#define B_DIM 256
#define N_DIM 65536
#define CHUNKS 16
#define TPB 256
#define NV 22   // 3 sum_s, 3 sum_t, 1 sum_w, 3 sum_ws, 3 sum_wt, 9 sum_w_s_t

__device__ float g_scratch[B_DIM * CHUNKS * NV];

// ---------------------------------------------------------------------------
// Kernel 1: per-(batch,chunk) partial reduction. grid = B*CHUNKS = 4096,
// 4 float4 iterations per thread per stream (hot loop identical to R6).
// ---------------------------------------------------------------------------
__global__ __launch_bounds__(TPB) void svd_reduce_kernel(
    const float* __restrict__ src,
    const float* __restrict__ tgt,
    const float* __restrict__ wgt)
{
    const int bc = blockIdx.x;
    const int b = bc >> 4;          // CHUNKS = 16
    const int c = bc & 15;

    const float4* s0 = (const float4*)(src + (size_t)b * 3 * N_DIM);
    const float4* s1 = s0 + (N_DIM / 4);
    const float4* s2 = s0 + 2 * (N_DIM / 4);
    const float4* t0 = (const float4*)(tgt + (size_t)b * 3 * N_DIM);
    const float4* t1 = t0 + (N_DIM / 4);
    const float4* t2 = t0 + 2 * (N_DIM / 4);
    const float4* w4 = (const float4*)(wgt + (size_t)b * N_DIM);

    // N/4 = 16384 float4 per row; per chunk: 1024 float4; per thread: 4.
    const int base = c * (N_DIM / 4 / CHUNKS) + threadIdx.x;

    float a[NV];
#pragma unroll
    for (int k = 0; k < NV; k++) a[k] = 0.0f;

#define ACC_ONE(sx, sy, sz, tx, ty, tz, ww)                               \
    {                                                                     \
        a[0] += (sx); a[1] += (sy); a[2] += (sz);                         \
        a[3] += (tx); a[4] += (ty); a[5] += (tz);                         \
        a[6] += (ww);                                                     \
        float ws0 = (ww) * (sx), ws1 = (ww) * (sy), ws2 = (ww) * (sz);    \
        a[7] += ws0; a[8] += ws1; a[9] += ws2;                            \
        a[10] += (ww) * (tx); a[11] += (ww) * (ty); a[12] += (ww) * (tz); \
        a[13] += ws0 * (tx); a[14] += ws0 * (ty); a[15] += ws0 * (tz);    \
        a[16] += ws1 * (tx); a[17] += ws1 * (ty); a[18] += ws1 * (tz);    \
        a[19] += ws2 * (tx); a[20] += ws2 * (ty); a[21] += ws2 * (tz);    \
    }

#pragma unroll
    for (int k = 0; k < 4; k++) {
        const int idx = base + k * TPB;
        float4 vs0 = s0[idx], vs1 = s1[idx], vs2 = s2[idx];
        float4 vt0 = t0[idx], vt1 = t1[idx], vt2 = t2[idx];
        float4 vw  = w4[idx];
        ACC_ONE(vs0.x, vs1.x, vs2.x, vt0.x, vt1.x, vt2.x, vw.x);
        ACC_ONE(vs0.y, vs1.y, vs2.y, vt0.y, vt1.y, vt2.y, vw.y);
        ACC_ONE(vs0.z, vs1.z, vs2.z, vt0.z, vt1.z, vt2.z, vw.z);
        ACC_ONE(vs0.w, vs1.w, vs2.w, vt0.w, vt1.w, vt2.w, vw.w);
    }
#undef ACC_ONE

#pragma unroll
    for (int off = 16; off > 0; off >>= 1) {
#pragma unroll
        for (int k = 0; k < NV; k++)
            a[k] += __shfl_down_sync(0xFFFFFFFFu, a[k], off);
    }

    __shared__ float smem[TPB / 32][NV];
    const int warp = threadIdx.x >> 5;
    const int lane = threadIdx.x & 31;
    if (lane == 0) {
#pragma unroll
        for (int k = 0; k < NV; k++) smem[warp][k] = a[k];
    }
    __syncthreads();

    if (threadIdx.x < NV) {
        float s = 0.0f;
#pragma unroll
        for (int wgi = 0; wgi < TPB / 32; wgi++) s += smem[wgi][threadIdx.x];
        g_scratch[(size_t)bc * NV + threadIdx.x] = s;
    }
}

// ---------------------------------------------------------------------------
// Kernel 2: 64 blocks x 128 threads; warp w solves batch blockIdx*4 + w.
// Single wave; no smem, no __syncthreads (R14-proven).
// ---------------------------------------------------------------------------
__global__ __launch_bounds__(128) void svd_solve_kernel(float* __restrict__ out)
{
    const int wid  = threadIdx.x >> 5;
    const int lane = threadIdx.x & 31;
    const int b    = blockIdx.x * 4 + wid;

    // Lanes 0..21 each sum their statistic over the 16 chunks (L2 hits),
    // then 22 shfls deliver all statistics to lane 0.
    float s = 0.0f;
    if (lane < NV) {
#pragma unroll
        for (int c = 0; c < CHUNKS; c++)
            s += g_scratch[((size_t)b * CHUNKS + c) * NV + lane];
    }

    float sums[NV];
#pragma unroll
    for (int k = 0; k < NV; k++)
        sums[k] = __shfl_sync(0xFFFFFFFFu, s, k);

    if (lane != 0) return;

    const float invN = 1.0f / (float)N_DIM;
    float ms[3], mt[3], Sws[3], Swt[3], Sw, M[3][3];
#pragma unroll
    for (int i = 0; i < 3; i++) {
        ms[i]  = sums[i] * invN;
        mt[i]  = sums[3 + i] * invN;
        Sws[i] = sums[7 + i];
        Swt[i] = sums[10 + i];
    }
    Sw = sums[6];
#pragma unroll
    for (int i = 0; i < 3; i++)
#pragma unroll
        for (int j = 0; j < 3; j++)
            M[i][j] = sums[13 + i * 3 + j];

    // H_ij = sum w s_i t_j - ms_i*sum(w t_j) - mt_j*sum(w s_i) + ms_i mt_j sum(w)
    float H[3][3];
#pragma unroll
    for (int i = 0; i < 3; i++)
#pragma unroll
        for (int j = 0; j < 3; j++)
            H[i][j] = M[i][j] - ms[i] * Swt[j] - mt[j] * Sws[i] + ms[i] * mt[j] * Sw;

    // S = H^T H (symmetric PSD)
    float S[3][3];
#pragma unroll
    for (int i = 0; i < 3; i++)
#pragma unroll
        for (int j = 0; j < 3; j++) {
            float acc = 0.0f;
#pragma unroll
            for (int k = 0; k < 3; k++) acc += H[k][i] * H[k][j];
            S[i][j] = acc;
        }

    const float trS = S[0][0] + S[1][1] + S[2][2];
    const float tol = 1e-13f * trS * trS + 1e-35f;

    // Cyclic Jacobi eigen-decomposition in fp32: S = V diag(l) V^T.
    float V[3][3] = {{1, 0, 0}, {0, 1, 0}, {0, 0, 1}};
    for (int sweep = 0; sweep < 5; sweep++) {
        float offm = S[0][1] * S[0][1] + S[0][2] * S[0][2] + S[1][2] * S[1][2];
        if (offm < tol) break;
#pragma unroll
        for (int pq = 0; pq < 3; pq++) {
            const int p = (pq == 2) ? 1 : 0;
            const int q = (pq == 0) ? 1 : 2;
            float apq = S[p][q];
            if (fabsf(apq) < 1e-30f) continue;
            float theta = (S[q][q] - S[p][p]) * __fdividef(0.5f, apq);
            float t = copysignf(1.0f, theta) *
                      __fdividef(1.0f, fabsf(theta) + sqrtf(theta * theta + 1.0f));
            float cth = rsqrtf(1.0f + t * t);
            float sth = t * cth;
            float app = S[p][p], aqq = S[q][q];
            S[p][p] = app - t * apq;
            S[q][q] = aqq + t * apq;
            S[p][q] = S[q][p] = 0.0f;
            const int r = 3 - p - q;
            float arp = S[r][p], arq = S[r][q];
            S[r][p] = S[p][r] = cth * arp - sth * arq;
            S[r][q] = S[q][r] = sth * arp + cth * arq;
#pragma unroll
            for (int k = 0; k < 3; k++) {
                float vkp = V[k][p], vkq = V[k][q];
                V[k][p] = cth * vkp - sth * vkq;
                V[k][q] = sth * vkp + cth * vkq;
            }
        }
    }

    // Sort eigenvalues descending; take top-2 eigenvectors.
    float lam[3] = {S[0][0], S[1][1], S[2][2]};
    int i0 = 0, i1 = 1, i2 = 2, tmp;
    if (lam[i0] < lam[i1]) { tmp = i0; i0 = i1; i1 = tmp; }
    if (lam[i0] < lam[i2]) { tmp = i0; i0 = i2; i2 = tmp; }
    if (lam[i1] < lam[i2]) { tmp = i1; i1 = i2; i2 = tmp; }

    float v1[3] = {V[0][i0], V[1][i0], V[2][i0]};
    float v2[3] = {V[0][i1], V[1][i1], V[2][i1]};
    float v3[3] = {v1[1] * v2[2] - v1[2] * v2[1],
                   v1[2] * v2[0] - v1[0] * v2[2],
                   v1[0] * v2[1] - v1[1] * v2[0]};

    // u1 = normalize(H v1); u2 = normalize(GS(H v2, u1)); u3 = u1 x u2.
    float u1[3], u2[3], u3[3];
#pragma unroll
    for (int i = 0; i < 3; i++)
        u1[i] = H[i][0] * v1[0] + H[i][1] * v1[1] + H[i][2] * v1[2];
    float in1 = rsqrtf(u1[0] * u1[0] + u1[1] * u1[1] + u1[2] * u1[2] + 1e-35f);
#pragma unroll
    for (int i = 0; i < 3; i++) u1[i] *= in1;

#pragma unroll
    for (int i = 0; i < 3; i++)
        u2[i] = H[i][0] * v2[0] + H[i][1] * v2[1] + H[i][2] * v2[2];
    float d12 = u2[0] * u1[0] + u2[1] * u1[1] + u2[2] * u1[2];
#pragma unroll
    for (int i = 0; i < 3; i++) u2[i] -= d12 * u1[i];
    float in2 = rsqrtf(u2[0] * u2[0] + u2[1] * u2[1] + u2[2] * u2[2] + 1e-35f);
#pragma unroll
    for (int i = 0; i < 3; i++) u2[i] *= in2;

    u3[0] = u1[1] * u2[2] - u1[2] * u2[1];
    u3[1] = u1[2] * u2[0] - u1[0] * u2[2];
    u3[2] = u1[0] * u2[1] - u1[1] * u2[0];

    // R = v1 u1^T + v2 u2^T + v3 u3^T (proper rotation, det=+1).
    float R[3][3];
#pragma unroll
    for (int i = 0; i < 3; i++)
#pragma unroll
        for (int j = 0; j < 3; j++)
            R[i][j] = v1[i] * u1[j] + v2[i] * u2[j] + v3[i] * u3[j];

    // t = -R @ src_mean + tgt_mean ; t_out = -R^T t ; Rt = R^T
    float tv[3];
#pragma unroll
    for (int i = 0; i < 3; i++)
        tv[i] = -(R[i][0] * ms[0] + R[i][1] * ms[1] + R[i][2] * ms[2]) + mt[i];

    float* outR = out + (size_t)b * 9;
    float* outT = out + (size_t)B_DIM * 9 + (size_t)b * 3;
#pragma unroll
    for (int i = 0; i < 3; i++) {
#pragma unroll
        for (int j = 0; j < 3; j++)
            outR[i * 3 + j] = R[j][i];  // Rt = R^T
        outT[i] = -(R[0][i] * tv[0] + R[1][i] * tv[1] + R[2][i] * tv[2]);
    }
}

extern "C" void kernel_launch(void* const* d_in, const int* in_sizes, int n_in,
                              void* d_out, int out_size)
{
    const float* src = (const float*)d_in[0];
    const float* tgt = (const float*)d_in[1];
    const float* wgt = (const float*)d_in[2];
    float* out = (float*)d_out;

    svd_reduce_kernel<<<B_DIM * CHUNKS, TPB>>>(src, tgt, wgt);
    svd_solve_kernel<<<B_DIM / 4, 128>>>(out);
}